// round 1
// baseline (speedup 1.0000x reference)
#include <cuda_runtime.h>
#include <cstdint>

#define NPTS 16384
#define DIM  128
#define NQ   16384
#define NV   64

#define BQ 128
#define BN 128
#define BK 16
#define AS 132              // Aq row stride (floats), keeps 16B alignment + de-conflicts
#define NSTAGE (128 * 8)    // 128 N-tiles * 8 k-chunks

__device__ float g_psq[NPTS];

// ---------- helpers ----------
__device__ __forceinline__ float lo32(unsigned long long v) {
    return __uint_as_float((unsigned)v);
}
__device__ __forceinline__ float hi32(unsigned long long v) {
    return __uint_as_float((unsigned)(v >> 32));
}
__device__ __forceinline__ unsigned long long dup2(float x) {
    unsigned long long r;
    asm("mov.b64 %0, {%1, %1};" : "=l"(r) : "f"(x));
    return r;
}
__device__ __forceinline__ void fma2(unsigned long long& d, unsigned long long a, unsigned long long b) {
    asm("fma.rn.f32x2 %0, %1, %2, %0;" : "+l"(d) : "l"(a), "l"(b));
}

// ---------- kernel 1: |p|^2 per point ----------
__global__ void psq_kernel(const float* __restrict__ points) {
    int warp = (blockIdx.x * blockDim.x + threadIdx.x) >> 5;
    int lane = threadIdx.x & 31;
    if (warp >= NPTS) return;
    const float4* row = (const float4*)(points + (size_t)warp * DIM);
    float4 v = row[lane];
    float s = v.x * v.x + v.y * v.y + v.z * v.z + v.w * v.w;
    #pragma unroll
    for (int o = 16; o; o >>= 1) s += __shfl_xor_sync(0xffffffffu, s, o);
    if (lane == 0) g_psq[warp] = s;
}

// ---------- kernel 2: fused dist-GEMM + argmin + gather ----------
__global__ __launch_bounds__(256)
void nn_kernel(const float* __restrict__ points,
               const float* __restrict__ points_q,
               const float* __restrict__ values,
               float* __restrict__ out) {
    extern __shared__ float smem[];
    float* Aq   = smem;                     // [DIM][AS], transposed: Aq[k*AS + q]
    float* Bs   = smem + DIM * AS;          // 2 buffers of [BK][BN]
    float* redV = Bs + 2 * BK * BN;         // [BQ][16]
    int*   redI = (int*)(redV + BQ * 16);   // [BQ][16]
    int*   nnId = redI + BQ * 16;           // [BQ]

    const int tid = threadIdx.x;
    const int tx = tid & 15;                // n-direction
    const int ty = tid >> 4;                // q-direction
    const int qBase = blockIdx.x * BQ;

    // ---- load Q tile, transposed into Aq (one-time) ----
    {
        const float4* qf4 = (const float4*)points_q;
        #pragma unroll
        for (int it = 0; it < 16; it++) {
            int f4 = tid + it * 256;        // 4096 float4 = 128x128 floats
            int q  = f4 >> 5;               // 32 float4 per row
            int k4 = f4 & 31;
            float4 v = qf4[(size_t)(qBase + q) * 32 + k4];
            Aq[(k4 * 4 + 0) * AS + q] = v.x;
            Aq[(k4 * 4 + 1) * AS + q] = v.y;
            Aq[(k4 * 4 + 2) * AS + q] = v.z;
            Aq[(k4 * 4 + 3) * AS + q] = v.w;
        }
    }

    // per-thread running best over its 8 q-rows
    float best[8];
    int   bestI[8];
    #pragma unroll
    for (int i = 0; i < 8; i++) { best[i] = 3.4e38f; bestI[i] = 0x7fffffff; }

    // packed accumulators: acc[p][j] holds (dot for q=ty*8+2p, q=ty*8+2p+1) vs n=tx*8+j
    unsigned long long acc[4][8];
    #pragma unroll
    for (int p = 0; p < 4; p++)
        #pragma unroll
        for (int j = 0; j < 8; j++) acc[p][j] = 0ull;

    const float4* pf4 = (const float4*)points;

    // global-load index decomposition (fixed per thread)
    const int f4a = tid * 2, f4b = tid * 2 + 1;
    const int n0 = f4a >> 2, kq0 = f4a & 3;     // 4 float4 per row-chunk of 16 floats
    const int n1 = f4b >> 2, kq1 = f4b & 3;

    // ---- prologue: stage 0 ----
    float4 ra, rb;
    {
        ra = pf4[(size_t)n0 * 32 + kq0];        // tile 0, kc 0
        rb = pf4[(size_t)n1 * 32 + kq1];
        Bs[(kq0 * 4 + 0) * BN + n0] = ra.x;
        Bs[(kq0 * 4 + 1) * BN + n0] = ra.y;
        Bs[(kq0 * 4 + 2) * BN + n0] = ra.z;
        Bs[(kq0 * 4 + 3) * BN + n0] = ra.w;
        Bs[(kq1 * 4 + 0) * BN + n1] = rb.x;
        Bs[(kq1 * 4 + 1) * BN + n1] = rb.y;
        Bs[(kq1 * 4 + 2) * BN + n1] = rb.z;
        Bs[(kq1 * 4 + 3) * BN + n1] = rb.w;
    }
    __syncthreads();

    for (int s = 0; s < NSTAGE; s++) {
        const int buf = s & 1;
        // prefetch next stage into registers
        float4 na, nb;
        if (s + 1 < NSTAGE) {
            int t1 = (s + 1) >> 3, kc1 = (s + 1) & 7;
            na = pf4[(size_t)(t1 * BN + n0) * 32 + kc1 * 4 + kq0];
            nb = pf4[(size_t)(t1 * BN + n1) * 32 + kc1 * 4 + kq1];
        }

        // compute 16 k-steps from Bs[buf]
        const int kc = s & 7;
        const float* bbase = Bs + buf * (BK * BN);
        #pragma unroll
        for (int kk = 0; kk < BK; kk++) {
            const float* arow = Aq + (kc * BK + kk) * AS + ty * 8;
            unsigned long long a0 = *(const unsigned long long*)(arow + 0);
            unsigned long long a1 = *(const unsigned long long*)(arow + 2);
            unsigned long long a2 = *(const unsigned long long*)(arow + 4);
            unsigned long long a3 = *(const unsigned long long*)(arow + 6);
            const float4* brow = (const float4*)(bbase + kk * BN + tx * 8);
            float4 b0 = brow[0], b1 = brow[1];
            unsigned long long bd[8];
            bd[0] = dup2(b0.x); bd[1] = dup2(b0.y); bd[2] = dup2(b0.z); bd[3] = dup2(b0.w);
            bd[4] = dup2(b1.x); bd[5] = dup2(b1.y); bd[6] = dup2(b1.z); bd[7] = dup2(b1.w);
            #pragma unroll
            for (int j = 0; j < 8; j++) {
                fma2(acc[0][j], a0, bd[j]);
                fma2(acc[1][j], a1, bd[j]);
                fma2(acc[2][j], a2, bd[j]);
                fma2(acc[3][j], a3, bd[j]);
            }
        }

        // write next stage into the other buffer
        if (s + 1 < NSTAGE) {
            float* wb = Bs + ((s + 1) & 1) * (BK * BN);
            wb[(kq0 * 4 + 0) * BN + n0] = na.x;
            wb[(kq0 * 4 + 1) * BN + n0] = na.y;
            wb[(kq0 * 4 + 2) * BN + n0] = na.z;
            wb[(kq0 * 4 + 3) * BN + n0] = na.w;
            wb[(kq1 * 4 + 0) * BN + n1] = nb.x;
            wb[(kq1 * 4 + 1) * BN + n1] = nb.y;
            wb[(kq1 * 4 + 2) * BN + n1] = nb.z;
            wb[(kq1 * 4 + 3) * BN + n1] = nb.w;
        }

        // end of an N-tile: fold argmin, reset accumulators
        if ((s & 7) == 7) {
            const int tile = s >> 3;
            const int nBase = tile * BN + tx * 8;
            float4 pq0 = *(const float4*)(g_psq + nBase);
            float4 pq1 = *(const float4*)(g_psq + nBase + 4);
            float ps[8] = {pq0.x, pq0.y, pq0.z, pq0.w, pq1.x, pq1.y, pq1.z, pq1.w};
            #pragma unroll
            for (int j = 0; j < 8; j++) {
                const int n = nBase + j;
                #pragma unroll
                for (int p = 0; p < 4; p++) {
                    float s0 = ps[j] - 2.0f * lo32(acc[p][j]);
                    float s1 = ps[j] - 2.0f * hi32(acc[p][j]);
                    if (s0 < best[2 * p])     { best[2 * p] = s0;     bestI[2 * p] = n; }
                    if (s1 < best[2 * p + 1]) { best[2 * p + 1] = s1; bestI[2 * p + 1] = n; }
                    acc[p][j] = 0ull;
                }
            }
        }

        __syncthreads();
    }

    // ---- cross-thread argmin reduction ----
    #pragma unroll
    for (int i = 0; i < 8; i++) {
        redV[(ty * 8 + i) * 16 + tx] = best[i];
        redI[(ty * 8 + i) * 16 + tx] = bestI[i];
    }
    __syncthreads();

    if (tid < BQ) {
        int q = tid;
        float bv = redV[q * 16];
        int   bi = redI[q * 16];
        #pragma unroll
        for (int t = 1; t < 16; t++) {
            float v = redV[q * 16 + t];
            int   idx = redI[q * 16 + t];
            if (v < bv || (v == bv && idx < bi)) { bv = v; bi = idx; }
        }
        nnId[q] = bi;
    }
    __syncthreads();

    // ---- gather values[nn] -> out ----
    {
        const float4* vf4 = (const float4*)values;   // 16 float4 per row (V=64)
        float4* of4 = (float4*)out;
        int q = tid >> 1, half = tid & 1;
        int nn = nnId[q];
        #pragma unroll
        for (int i = 0; i < 8; i++) {
            of4[(size_t)(qBase + q) * 16 + half * 8 + i] =
                vf4[(size_t)nn * 16 + half * 8 + i];
        }
    }
}

// ---------- launch ----------
extern "C" void kernel_launch(void* const* d_in, const int* in_sizes, int n_in,
                              void* d_out, int out_size) {
    const float* points   = (const float*)d_in[0];   // [16384,128]
    const float* values   = (const float*)d_in[1];   // [16384,64]
    const float* points_q = (const float*)d_in[2];   // [16384,128]
    float* out = (float*)d_out;                      // [16384,64]

    // p_sq
    psq_kernel<<<(NPTS * 32) / 256, 256>>>(points);

    // fused NN + gather
    const int smemFloats = DIM * AS + 2 * BK * BN + BQ * 16 + BQ * 16 + BQ;
    const int smemBytes = smemFloats * 4;  // ~100.9 KB
    static bool attrSet = false;           // attribute is idempotent config, not work
    cudaFuncSetAttribute(nn_kernel, cudaFuncAttributeMaxDynamicSharedMemorySize, smemBytes);
    nn_kernel<<<NQ / BQ, 256, smemBytes>>>(points, points_q, values, out);
    (void)attrSet; (void)in_sizes; (void)n_in; (void)out_size;
}

// round 3
// speedup vs baseline: 4.2828x; 4.2828x over previous
#include <cuda_runtime.h>
#include <cuda_bf16.h>
#include <cstdint>

#define NPTS 16384
#define DIM  128
#define NQ   16384
#define NV   64

#define BQ    128
#define BN    128
#define NTILE (NPTS / BN)
#define EPS   0.75f
#define CAP   12288

// ---------------- device globals ----------------
__device__ __nv_bfloat16 g_pb[NPTS * DIM];
__device__ __nv_bfloat16 g_qb[NQ * DIM];
__device__ float         g_psq[NPTS];

// ---------------- SMEM layout (bytes) ----------------
#define SM_A     0        // 128x128 bf16, swizzled            (32768)
#define SM_B     32768    // 2 x 32768
#define SM_PSQ   98304    // 2 x 512
#define SM_CURB  99328    // 128 x u32 orderable running best
#define SM_CNT   99840    // counter (+pad)
#define SM_CAND  99856    // CAP x u32                          (49152) -> ends 149008
#define SM_WIN   149008   // 128 x u64                          (1024)
#define SM_TOTAL 150032

// ---------------- helpers ----------------
__device__ __forceinline__ uint32_t smem_u32(const void* p) {
    uint32_t a;
    asm("{ .reg .u64 t; cvta.to.shared.u64 t, %1; cvt.u32.u64 %0, t; }" : "=r"(a) : "l"(p));
    return a;
}
__device__ __forceinline__ unsigned toOrd(float f) {
    unsigned u = __float_as_uint(f);
    return (u & 0x80000000u) ? ~u : (u | 0x80000000u);
}
__device__ __forceinline__ float fromOrd(unsigned u) {
    unsigned v = (u & 0x80000000u) ? (u & 0x7fffffffu) : ~u;
    return __uint_as_float(v);
}

#define CP_ASYNC16(d, s) asm volatile("cp.async.cg.shared.global [%0], [%1], 16;" :: "r"(d), "l"(s) : "memory")

#define LDSM4(r0, r1, r2, r3, addr) \
    asm volatile("ldmatrix.sync.aligned.m8n8.x4.shared.b16 {%0,%1,%2,%3}, [%4];" \
                 : "=r"(r0), "=r"(r1), "=r"(r2), "=r"(r3) : "r"(addr))

#define MMA16816(c, a, b) \
    asm volatile("mma.sync.aligned.m16n8k16.row.col.f32.bf16.bf16.f32 " \
                 "{%0,%1,%2,%3}, {%4,%5,%6,%7}, {%8,%9}, {%0,%1,%2,%3};" \
                 : "+f"((c)[0]), "+f"((c)[1]), "+f"((c)[2]), "+f"((c)[3]) \
                 : "r"((a)[0]), "r"((a)[1]), "r"((a)[2]), "r"((a)[3]), \
                   "r"((b)[0]), "r"((b)[1]))

// ---------------- kernel 0: fp32 -> bf16 ----------------
__global__ void cvt_kernel(const float* __restrict__ pts, const float* __restrict__ qs) {
    int i = blockIdx.x * blockDim.x + threadIdx.x;   // uint4 index (8 bf16)
    const int half = NPTS * DIM / 8;
    const float4* src;
    __nv_bfloat16* dst;
    int j = i;
    if (i < half) { src = (const float4*)pts; dst = g_pb; }
    else          { src = (const float4*)qs;  dst = g_qb; j = i - half; }
    float4 a = src[(size_t)j * 2], b = src[(size_t)j * 2 + 1];
    __nv_bfloat162 p0 = __floats2bfloat162_rn(a.x, a.y);
    __nv_bfloat162 p1 = __floats2bfloat162_rn(a.z, a.w);
    __nv_bfloat162 p2 = __floats2bfloat162_rn(b.x, b.y);
    __nv_bfloat162 p3 = __floats2bfloat162_rn(b.z, b.w);
    uint4 o;
    o.x = *reinterpret_cast<uint32_t*>(&p0);
    o.y = *reinterpret_cast<uint32_t*>(&p1);
    o.z = *reinterpret_cast<uint32_t*>(&p2);
    o.w = *reinterpret_cast<uint32_t*>(&p3);
    reinterpret_cast<uint4*>(dst)[j] = o;
}

// ---------------- kernel 1: |p|^2 ----------------
__global__ void psq_kernel(const float* __restrict__ points) {
    int warp = (blockIdx.x * blockDim.x + threadIdx.x) >> 5;
    int lane = threadIdx.x & 31;
    if (warp >= NPTS) return;
    const float4* row = (const float4*)(points + (size_t)warp * DIM);
    float4 v = row[lane];
    float s = v.x * v.x + v.y * v.y + v.z * v.z + v.w * v.w;
    #pragma unroll
    for (int o = 16; o; o >>= 1) s += __shfl_xor_sync(0xffffffffu, s, o);
    if (lane == 0) g_psq[warp] = s;
}

// ---------------- B-tile producer ----------------
__device__ __forceinline__ void issue_tile(uint32_t sb, int t, int b, int tid) {
    const char* srcB = (const char*)(g_pb + (size_t)t * BN * DIM);
    #pragma unroll
    for (int it = 0; it < 8; it++) {
        int idx = it * 256 + tid;
        int r = idx >> 4, c = idx & 15;
        CP_ASYNC16(sb + SM_B + b * 32768 + r * 256 + ((c ^ (r & 7)) << 4),
                   srcB + (size_t)r * 256 + c * 16);
    }
    if (tid < 32)
        CP_ASYNC16(sb + SM_PSQ + b * 512 + tid * 16,
                   (const char*)(g_psq + (size_t)t * BN) + tid * 16);
}

// ---------------- kernel 2: HMMA NN search ----------------
__global__ __launch_bounds__(256, 1)
void nn_main(const float* __restrict__ points,
             const float* __restrict__ points_q,
             const float* __restrict__ values,
             float* __restrict__ out) {
    extern __shared__ char smem[];
    const uint32_t sb = smem_u32(smem);
    unsigned* curB = (unsigned*)(smem + SM_CURB);
    unsigned* cntP = (unsigned*)(smem + SM_CNT);
    unsigned* cand = (unsigned*)(smem + SM_CAND);
    unsigned long long* win = (unsigned long long*)(smem + SM_WIN);
    const float* psqS = (const float*)(smem + SM_PSQ);

    const int tid = threadIdx.x, wid = tid >> 5, lane = tid & 31;
    const int warpM = (wid >> 2) * 64, warpN = (wid & 3) * 32;
    const int qBase = blockIdx.x * BQ;

    if (tid < BQ) { curB[tid] = toOrd(3.0e38f); win[tid] = ~0ull; }
    if (tid == 0) *cntP = 0;

    // A tile (queries): swizzled SMEM via cp.async
    {
        const char* src = (const char*)(g_qb + (size_t)qBase * DIM);
        #pragma unroll
        for (int it = 0; it < 8; it++) {
            int idx = it * 256 + tid;
            int r = idx >> 4, c = idx & 15;
            CP_ASYNC16(sb + SM_A + r * 256 + ((c ^ (r & 7)) << 4),
                       src + (size_t)r * 256 + c * 16);
        }
    }
    issue_tile(sb, 0, 0, tid);
    asm volatile("cp.async.commit_group;" ::: "memory");
    asm volatile("cp.async.wait_group 0;" ::: "memory");
    __syncthreads();

    // per-thread ldmatrix address precompute
    uint32_t aB[4], aX[4];
    #pragma unroll
    for (int m = 0; m < 4; m++) {
        int r = warpM + m * 16 + (lane & 15);
        aB[m] = sb + SM_A + r * 256;
        aX[m] = r & 7;
    }
    const int aHi = lane >> 4;
    uint32_t bOf[2], bX[2];
    #pragma unroll
    for (int p = 0; p < 2; p++) {
        int n = warpN + p * 16 + (lane & 7) + ((lane >> 4) << 3);
        bOf[p] = n * 256;
        bX[p] = n & 7;
    }
    const int bHi = (lane >> 3) & 1;

    for (int t = 0; t < NTILE; t++) {
        const int b = t & 1;
        if (t + 1 < NTILE) {
            issue_tile(sb, t + 1, b ^ 1, tid);
            asm volatile("cp.async.commit_group;" ::: "memory");
        }

        float acc[4][4][4];
        #pragma unroll
        for (int m = 0; m < 4; m++)
            #pragma unroll
            for (int n = 0; n < 4; n++)
                #pragma unroll
                for (int k = 0; k < 4; k++) acc[m][n][k] = 0.0f;

        const uint32_t bBase = sb + SM_B + b * 32768;
        #pragma unroll
        for (int ks = 0; ks < 8; ks++) {
            uint32_t af[4][4], bf[2][4];
            #pragma unroll
            for (int m = 0; m < 4; m++)
                LDSM4(af[m][0], af[m][1], af[m][2], af[m][3],
                      aB[m] + ((((ks << 1) + aHi) ^ aX[m]) << 4));
            #pragma unroll
            for (int p = 0; p < 2; p++)
                LDSM4(bf[p][0], bf[p][1], bf[p][2], bf[p][3],
                      bBase + bOf[p] + ((((ks << 1) + bHi) ^ bX[p]) << 4));
            #pragma unroll
            for (int m = 0; m < 4; m++)
                #pragma unroll
                for (int n = 0; n < 4; n++)
                    MMA16816(acc[m][n], af[m], &bf[n >> 1][(n & 1) * 2]);
        }

        // ---- epilogue pass 1: per-row tile min -> shared running best ----
        float ps[4][2];
        #pragma unroll
        for (int n = 0; n < 4; n++) {
            int col = warpN + n * 8 + (lane & 3) * 2;
            ps[n][0] = psqS[b * 128 + col];
            ps[n][1] = psqS[b * 128 + col + 1];
        }
        float rowMin[4][2];
        #pragma unroll
        for (int m = 0; m < 4; m++)
            #pragma unroll
            for (int h = 0; h < 2; h++) {
                float mv = 3.0e38f;
                #pragma unroll
                for (int n = 0; n < 4; n++) {
                    mv = fminf(mv, fmaf(acc[m][n][h * 2 + 0], -2.0f, ps[n][0]));
                    mv = fminf(mv, fmaf(acc[m][n][h * 2 + 1], -2.0f, ps[n][1]));
                }
                rowMin[m][h] = mv;
                int r = warpM + m * 16 + (lane >> 2) + h * 8;
                if (toOrd(mv) < curB[r]) atomicMin(&curB[r], toOrd(mv));
            }
        __syncthreads();

        // ---- epilogue pass 2: push margin candidates ----
        #pragma unroll
        for (int m = 0; m < 4; m++)
            #pragma unroll
            for (int h = 0; h < 2; h++) {
                int r = warpM + m * 16 + (lane >> 2) + h * 8;
                float lim = fromOrd(curB[r]) + EPS;
                if (rowMin[m][h] < lim) {
                    #pragma unroll
                    for (int n = 0; n < 4; n++)
                        #pragma unroll
                        for (int j = 0; j < 2; j++) {
                            float s = fmaf(acc[m][n][h * 2 + j], -2.0f, ps[n][j]);
                            if (s < lim) {
                                unsigned slot = atomicAdd(cntP, 1u);
                                unsigned nIdx = (unsigned)(t * BN + warpN + n * 8 + (lane & 3) * 2 + j);
                                if (slot < CAP) cand[slot] = ((unsigned)r << 14) | nIdx;
                            }
                        }
                }
            }

        asm volatile("cp.async.wait_group 0;" ::: "memory");
        __syncthreads();
    }

    // ---- exact fp32 rescore ----
    unsigned total = *cntP;
    if (total > CAP) total = CAP;
    for (unsigned c = wid; c < total; c += 8) {
        unsigned pk = cand[c];
        int q = pk >> 14, n = pk & 16383;
        float4 qv = *(const float4*)(points_q + (size_t)(qBase + q) * DIM + lane * 4);
        float4 pv = *(const float4*)(points + (size_t)n * DIM + lane * 4);
        float d = qv.x * pv.x + qv.y * pv.y + qv.z * pv.z + qv.w * pv.w;
        #pragma unroll
        for (int o = 16; o; o >>= 1) d += __shfl_xor_sync(0xffffffffu, d, o);
        if (lane == 0) {
            float s = fmaf(d, -2.0f, g_psq[n]);
            unsigned long long key = ((unsigned long long)toOrd(s) << 32) | (unsigned)n;
            atomicMin(&win[q], key);
        }
    }
    __syncthreads();

    // ---- gather values ----
    for (int i = tid; i < BQ * 16; i += 256) {
        int q = i >> 4, c4 = i & 15;
        unsigned idx = (unsigned)(win[q] & 0xFFFFFFFFu);
        *(float4*)(out + (size_t)(qBase + q) * NV + c4 * 4) =
            *(const float4*)(values + (size_t)idx * NV + c4 * 4);
    }
}

// ---------------- launch ----------------
extern "C" void kernel_launch(void* const* d_in, const int* in_sizes, int n_in,
                              void* d_out, int out_size) {
    const float* points   = (const float*)d_in[0];   // [16384,128]
    const float* values   = (const float*)d_in[1];   // [16384,64]
    const float* points_q = (const float*)d_in[2];   // [16384,128]
    float* out = (float*)d_out;

    cvt_kernel<<<(2 * NPTS * DIM / 8) / 256, 256>>>(points, points_q);
    psq_kernel<<<(NPTS * 32) / 256, 256>>>(points);

    cudaFuncSetAttribute(nn_main, cudaFuncAttributeMaxDynamicSharedMemorySize, SM_TOTAL);
    nn_main<<<NQ / BQ, 256, SM_TOTAL>>>(points, points_q, values, out);
    (void)in_sizes; (void)n_in; (void)out_size;
}